// round 1
// baseline (speedup 1.0000x reference)
#include <cuda_runtime.h>
#include <cstdint>

// LogicGatedSNN: spikes = (membrane + x · (states > 50)^T + noise) >= threshold
// x: [1, 8192] fp32 (binary), states: [8192, 8192] fp32, out: [8192] fp32
//
// HBM-bound: 256 MiB single-pass stream of `states`. One CTA per output row.

#define IN_F   8192
#define OUT_F  8192
#define NTHR   256
#define VEC_PER_THREAD (IN_F / 4 / NTHR)   // 8 float4 per thread

__global__ __launch_bounds__(NTHR) void snn_row_kernel(
    const float* __restrict__ x,        // [IN_F]
    const float* __restrict__ states,   // [OUT_F, IN_F]
    const float* __restrict__ mem,      // [OUT_F]
    const float* __restrict__ thr,      // [OUT_F]
    const float* __restrict__ noise,    // [OUT_F]
    float* __restrict__ out)            // [OUT_F]
{
    __shared__ float xs[IN_F];          // 32 KiB
    __shared__ float wsum[NTHR / 32];

    const int tid = threadIdx.x;

    // Stage x into shared memory (coalesced float4)
    const float4* __restrict__ x4 = reinterpret_cast<const float4*>(x);
    float4* xs4 = reinterpret_cast<float4*>(xs);
    #pragma unroll
    for (int i = 0; i < IN_F / 4 / NTHR; ++i)
        xs4[i * NTHR + tid] = x4[i * NTHR + tid];
    __syncthreads();

    const int row = blockIdx.x;
    const float4* __restrict__ s4 =
        reinterpret_cast<const float4*>(states + (size_t)row * IN_F);

    float sum = 0.0f;
    #pragma unroll
    for (int j = 0; j < VEC_PER_THREAD; ++j) {
        const int idx = j * NTHR + tid;
        const float4 s  = s4[idx];           // coalesced 128B/warp, MLP=8
        const float4 xv = xs4[idx];
        sum += (s.x > 50.0f) ? xv.x : 0.0f;
        sum += (s.y > 50.0f) ? xv.y : 0.0f;
        sum += (s.z > 50.0f) ? xv.z : 0.0f;
        sum += (s.w > 50.0f) ? xv.w : 0.0f;
    }

    // Warp reduce
    #pragma unroll
    for (int off = 16; off > 0; off >>= 1)
        sum += __shfl_xor_sync(0xffffffffu, sum, off);

    if ((tid & 31) == 0) wsum[tid >> 5] = sum;
    __syncthreads();

    if (tid < 32) {
        float s = (tid < NTHR / 32) ? wsum[tid] : 0.0f;
        #pragma unroll
        for (int off = 4; off > 0; off >>= 1)
            s += __shfl_xor_sync(0xffffffffu, s, off);
        if (tid == 0) {
            const float p = mem[row] + s + noise[row];
            out[row] = (p >= thr[row]) ? 1.0f : 0.0f;
        }
    }
}

extern "C" void kernel_launch(void* const* d_in, const int* in_sizes, int n_in,
                              void* d_out, int out_size) {
    const float* x      = (const float*)d_in[0];  // spike_input [1, 8192]
    const float* states = (const float*)d_in[1];  // synapse_states [8192, 8192]
    const float* mem    = (const float*)d_in[2];  // membrane_potential [8192]
    const float* thr    = (const float*)d_in[3];  // adaptive_threshold [8192]
    const float* noise  = (const float*)d_in[4];  // noise [8192]
    float* out = (float*)d_out;                   // spikes [8192]

    snn_row_kernel<<<OUT_F, NTHR>>>(x, states, mem, thr, noise, out);
}

// round 2
// speedup vs baseline: 1.5351x; 1.5351x over previous
#include <cuda_runtime.h>
#include <cstdint>

// LogicGatedSNN: spikes = (membrane + x · (states > 50)^T + noise) >= threshold
// x: [8192] fp32 binary, states: [8192, 8192] fp32, out: [8192] fp32
//
// DRAM-bound: 256 MiB single-pass stream of `states`.
// R rows per CTA; x columns cached in REGISTERS (same columns for all rows),
// so L1 sees only the states stream + one x load per CTA.

#define IN_F   8192
#define OUT_F  8192
#define NTHR   256
#define ROWS_PER_CTA 4
#define VEC_PER_THREAD (IN_F / 4 / NTHR)   // 8 float4 per thread

__global__ __launch_bounds__(NTHR) void snn_rows_kernel(
    const float* __restrict__ x,        // [IN_F]
    const float* __restrict__ states,   // [OUT_F, IN_F]
    const float* __restrict__ mem,      // [OUT_F]
    const float* __restrict__ thr,      // [OUT_F]
    const float* __restrict__ noise,    // [OUT_F]
    float* __restrict__ out)            // [OUT_F]
{
    __shared__ float wsum[ROWS_PER_CTA][NTHR / 32];

    const int tid = threadIdx.x;
    const int row0 = blockIdx.x * ROWS_PER_CTA;

    // Load this thread's x columns into registers once (L1-hot after warmup).
    const float4* __restrict__ x4 = reinterpret_cast<const float4*>(x);
    float4 xv[VEC_PER_THREAD];
    #pragma unroll
    for (int j = 0; j < VEC_PER_THREAD; ++j)
        xv[j] = x4[j * NTHR + tid];

    float acc[ROWS_PER_CTA];

    #pragma unroll
    for (int r = 0; r < ROWS_PER_CTA; ++r) {
        const float4* __restrict__ s4 =
            reinterpret_cast<const float4*>(states + (size_t)(row0 + r) * IN_F);

        float4 s[VEC_PER_THREAD];
        #pragma unroll
        for (int j = 0; j < VEC_PER_THREAD; ++j)
            s[j] = s4[j * NTHR + tid];       // 8 independent LDG.128, MLP=8

        float sum = 0.0f;
        #pragma unroll
        for (int j = 0; j < VEC_PER_THREAD; ++j) {
            sum += (s[j].x > 50.0f) ? xv[j].x : 0.0f;
            sum += (s[j].y > 50.0f) ? xv[j].y : 0.0f;
            sum += (s[j].z > 50.0f) ? xv[j].z : 0.0f;
            sum += (s[j].w > 50.0f) ? xv[j].w : 0.0f;
        }
        acc[r] = sum;
    }

    // Warp reductions for all R rows
    #pragma unroll
    for (int r = 0; r < ROWS_PER_CTA; ++r) {
        float s = acc[r];
        #pragma unroll
        for (int off = 16; off > 0; off >>= 1)
            s += __shfl_xor_sync(0xffffffffu, s, off);
        if ((tid & 31) == 0) wsum[r][tid >> 5] = s;
    }
    __syncthreads();

    // First R threads finish cross-warp sums and write output
    if (tid < ROWS_PER_CTA) {
        float s = 0.0f;
        #pragma unroll
        for (int w = 0; w < NTHR / 32; ++w)
            s += wsum[tid][w];
        const int row = row0 + tid;
        const float p = mem[row] + s + noise[row];
        out[row] = (p >= thr[row]) ? 1.0f : 0.0f;
    }
}

extern "C" void kernel_launch(void* const* d_in, const int* in_sizes, int n_in,
                              void* d_out, int out_size) {
    const float* x      = (const float*)d_in[0];  // spike_input [1, 8192]
    const float* states = (const float*)d_in[1];  // synapse_states [8192, 8192]
    const float* mem    = (const float*)d_in[2];  // membrane_potential [8192]
    const float* thr    = (const float*)d_in[3];  // adaptive_threshold [8192]
    const float* noise  = (const float*)d_in[4];  // noise [8192]
    float* out = (float*)d_out;                   // spikes [8192]

    snn_rows_kernel<<<OUT_F / ROWS_PER_CTA, NTHR>>>(x, states, mem, thr, noise, out);
}

// round 3
// speedup vs baseline: 1.6436x; 1.0707x over previous
#include <cuda_runtime.h>
#include <cstdint>

// LogicGatedSNN: spikes = (membrane + x · (states > 50)^T + noise) >= threshold
// x: [8192] fp32 binary, states: [8192, 8192] fp32, out: [8192] fp32
//
// DRAM-bound: 256 MiB single-pass stream of `states` (~38us floor at ~6.9TB/s).
// One CTA per output row (fine granularity -> minimal wave-quantization/drain
// loss). x fetched per-CTA via __ldg (L1-resident, 22%-busy L1 absorbs it);
// states streamed with __ldcs (single-use, evict-first).

#define IN_F   8192
#define OUT_F  8192
#define NTHR   256
#define VEC_PER_THREAD (IN_F / 4 / NTHR)   // 8 float4 per thread

__global__ __launch_bounds__(NTHR) void snn_row1_kernel(
    const float* __restrict__ x,        // [IN_F]
    const float* __restrict__ states,   // [OUT_F, IN_F]
    const float* __restrict__ mem,      // [OUT_F]
    const float* __restrict__ thr,      // [OUT_F]
    const float* __restrict__ noise,    // [OUT_F]
    float* __restrict__ out)            // [OUT_F]
{
    __shared__ float wsum[NTHR / 32];

    const int tid = threadIdx.x;
    const int row = blockIdx.x;

    const float4* __restrict__ x4 = reinterpret_cast<const float4*>(x);
    const float4* __restrict__ s4 =
        reinterpret_cast<const float4*>(states + (size_t)row * IN_F);

    // x columns for this thread (L1-hot after first CTA on each SM)
    float4 xv[VEC_PER_THREAD];
    #pragma unroll
    for (int j = 0; j < VEC_PER_THREAD; ++j)
        xv[j] = __ldg(&x4[j * NTHR + tid]);

    // states row: 8 independent streaming LDG.128 per thread
    float4 s[VEC_PER_THREAD];
    #pragma unroll
    for (int j = 0; j < VEC_PER_THREAD; ++j)
        s[j] = __ldcs(&s4[j * NTHR + tid]);

    float sum = 0.0f;
    #pragma unroll
    for (int j = 0; j < VEC_PER_THREAD; ++j) {
        sum += (s[j].x > 50.0f) ? xv[j].x : 0.0f;
        sum += (s[j].y > 50.0f) ? xv[j].y : 0.0f;
        sum += (s[j].z > 50.0f) ? xv[j].z : 0.0f;
        sum += (s[j].w > 50.0f) ? xv[j].w : 0.0f;
    }

    // Warp reduce
    #pragma unroll
    for (int off = 16; off > 0; off >>= 1)
        sum += __shfl_xor_sync(0xffffffffu, sum, off);

    if ((tid & 31) == 0) wsum[tid >> 5] = sum;
    __syncthreads();

    if (tid == 0) {
        float s0 = 0.0f;
        #pragma unroll
        for (int w = 0; w < NTHR / 32; ++w)
            s0 += wsum[w];
        const float p = mem[row] + s0 + noise[row];
        out[row] = (p >= thr[row]) ? 1.0f : 0.0f;
    }
}

extern "C" void kernel_launch(void* const* d_in, const int* in_sizes, int n_in,
                              void* d_out, int out_size) {
    const float* x      = (const float*)d_in[0];  // spike_input [1, 8192]
    const float* states = (const float*)d_in[1];  // synapse_states [8192, 8192]
    const float* mem    = (const float*)d_in[2];  // membrane_potential [8192]
    const float* thr    = (const float*)d_in[3];  // adaptive_threshold [8192]
    const float* noise  = (const float*)d_in[4];  // noise [8192]
    float* out = (float*)d_out;                   // spikes [8192]

    snn_row1_kernel<<<OUT_F, NTHR>>>(x, states, mem, thr, noise, out);
}